// round 14
// baseline (speedup 1.0000x reference)
#include <cuda_runtime.h>
#include <cuda_bf16.h>
#include <cstdint>

// Problem constants (V=250000, H=128, N=32768, K=256).
#define HD      128
#define KS      256
#define THREADS 256
#define GRID    256              // each CTA owns 128 contiguous rows (2 x 64-row tiles)
#define LDBE    136              // padded row stride (bf16 elems): conflict-free ldmatrix
#define ROWB    (LDBE * 2)       // 272 bytes per row

// ---------------- smem layout (bytes) ----------------
#define OFF_B    0                        // B image 256 x 136 bf16   (69632 B)
#define OFF_A    69632                    // A image 128 x 136 bf16   (34816 B)
#define OFF_CBS  104448                   // float[256]
#define OFF_TIDX 105472                   // int[128]   target indices
#define OFF_TL   105984                   // float[128] target logits
#define OFF_RM   106496                   // float[64*4]
#define OFF_RS   107520                   // float[64*4]
#define OFF_RED  108544                   // float[256]
#define OFF_WRD  109568                   // float[2]
#define OFF_LAST 109576                   // int
#define SMEM_TOTAL 109600                 // x2 CTAs = 219.2 KB < 228 KB/SM

// ---------------- device globals (no allocation allowed) ----------------
__device__ float        g_partials[GRID];
__device__ unsigned int g_done;

// ---------------- helpers ----------------
__device__ __forceinline__ uint32_t smem_u32(const void* p) {
    uint32_t a;
    asm("{ .reg .u64 t; cvta.to.shared.u64 t, %1; cvt.u32.u64 %0, t; }" : "=r"(a) : "l"(p));
    return a;
}
__device__ __forceinline__ unsigned pk(float lo, float hi) {
    __nv_bfloat162 t = __floats2bfloat162_rn(lo, hi);
    return *reinterpret_cast<unsigned*>(&t);
}
#define LDSM4(r, a) \
    asm volatile("ldmatrix.sync.aligned.m8n8.x4.shared.b16 {%0,%1,%2,%3}, [%4];" \
        : "=r"((r)[0]), "=r"((r)[1]), "=r"((r)[2]), "=r"((r)[3]) : "r"(a))
__device__ __forceinline__ void mma_bf16(float* d, const uint32_t* a,
                                         uint32_t b0, uint32_t b1) {
    asm volatile("mma.sync.aligned.m16n8k16.row.col.f32.bf16.bf16.f32 "
                 "{%0,%1,%2,%3}, {%4,%5,%6,%7}, {%8,%9}, {%0,%1,%2,%3};"
                 : "+f"(d[0]), "+f"(d[1]), "+f"(d[2]), "+f"(d[3])
                 : "r"(a[0]), "r"(a[1]), "r"(a[2]), "r"(a[3]), "r"(b0), "r"(b1));
}

// int64-vs-int32 detection: int64 indices (<2^32) have all hi-words zero.
__device__ __forceinline__ int detect64(const void* idx, int lane) {
    unsigned hi = ((const unsigned*)idx)[2 * lane + 1];
    return __all_sync(0xffffffffu, hi == 0u);
}

// ---------------- single fused kernel: 2 CTAs/SM, 128 rows/CTA, 1 wave ----
__global__ __launch_bounds__(THREADS, 2)
void k_all(const float* __restrict__ weight, const float* __restrict__ bias,
           const float* __restrict__ hiddens, const float* __restrict__ nl,
           const void* __restrict__ targets, const void* __restrict__ samples,
           float* __restrict__ out, int N) {
    extern __shared__ __align__(16) char smem[];
    const int tid = threadIdx.x, w = tid >> 5, lane = tid & 31;
    const int row0 = blockIdx.x << 7;             // 128 rows per CTA
    const uint32_t sb = smem_u32(smem);
    float* cbs  = (float*)(smem + OFF_CBS);
    int*   tIdx = (int*)(smem + OFF_TIDX);
    float* tl   = (float*)(smem + OFF_TL);
    float* rm   = (float*)(smem + OFF_RM);
    float* rs   = (float*)(smem + OFF_RS);
    float* red  = (float*)(smem + OFF_RED);
    float* wrd  = (float*)(smem + OFF_WRD);
    int*   last = (int*)(smem + OFF_LAST);

    const int is64_t = detect64(targets, lane);   // warp-uniform
    const int is64_s = detect64(samples, lane);

    // ---------- Phase 1: one max-MLP load burst, one barrier ----------
    // Target indices (coalesced).
    if (tid < 128) {
        long long t = is64_t ? ((const long long*)targets)[row0 + tid]
                             : (long long)((const int*)targets)[row0 + tid];
        tIdx[tid] = (int)t;
    }
    // A fill: 128 rows fp32 hiddens -> bf16 padded image (independent LDGs).
#pragma unroll
    for (int it = 0; it < 16; it++) {
        int i = tid + it * THREADS;               // 4096 float4 chunks
        int r = i >> 5, c4 = i & 31;
        float4 v = ((const float4*)hiddens)[((size_t)(row0 + r)) * 32 + c4];
        *(uint2*)(smem + OFF_A + r * ROWB + c4 * 8) =
            make_uint2(pk(v.x, v.y), pk(v.z, v.w));
    }
    // B fill: gather sample weight rows -> bf16 padded image (L2-hot).
    for (int i = tid; i < KS * HD / 8; i += THREADS) {  // 4096 chunks of 8 elems
        int n = i >> 4, c = i & 15;
        long long s = is64_s ? ((const long long*)samples)[n]
                             : (long long)((const int*)samples)[n];
        const float4* wr = (const float4*)(weight + (size_t)s * HD);
        float4 a = wr[c * 2], b = wr[c * 2 + 1];
        *(uint4*)(smem + OFF_B + n * ROWB + c * 16) =
            make_uint4(pk(a.x, a.y), pk(a.z, a.w), pk(b.x, b.y), pk(b.z, b.w));
    }
    {
        long long s = is64_s ? ((const long long*)samples)[tid]
                             : (long long)((const int*)samples)[tid];
        cbs[tid] = bias[s] - nl[s];
    }
    if (tid == 0) *last = 0;
    __syncthreads();

    // ---------- Phase 2: target logits from smem bf16 A + batched gathers ----
    // Warp w owns rows w*16 .. w*16+15; two 8-deep batches keep 8 random
    // weight-row loads in flight before any shuffle consumes them.
#pragma unroll
    for (int b = 0; b < 2; b++) {
        int tt[8]; float4 wv[8]; uint2 hv[8]; float bn_[8];
#pragma unroll
        for (int j = 0; j < 8; j++) tt[j] = tIdx[w * 16 + b * 8 + j];
#pragma unroll
        for (int j = 0; j < 8; j++)
            wv[j] = ((const float4*)weight)[(size_t)tt[j] * 32 + lane];
#pragma unroll
        for (int j = 0; j < 8; j++) {
            int m = w * 16 + b * 8 + j;
            hv[j] = *(const uint2*)(smem + OFF_A + m * ROWB + lane * 8);
        }
#pragma unroll
        for (int j = 0; j < 8; j++) bn_[j] = __ldg(bias + tt[j]) - __ldg(nl + tt[j]);
#pragma unroll
        for (int j = 0; j < 8; j++) {
            __nv_bfloat162 h0 = *reinterpret_cast<__nv_bfloat162*>(&hv[j].x);
            __nv_bfloat162 h1 = *reinterpret_cast<__nv_bfloat162*>(&hv[j].y);
            float d = __bfloat162float(h0.x) * wv[j].x + __bfloat162float(h0.y) * wv[j].y
                    + __bfloat162float(h1.x) * wv[j].z + __bfloat162float(h1.y) * wv[j].w;
#pragma unroll
            for (int o = 16; o; o >>= 1) d += __shfl_xor_sync(0xffffffffu, d, o);
            if (lane == 0) tl[w * 16 + b * 8 + j] = d + bn_[j];
        }
    }
    // tl consumed only after the epilogue barrier below — no extra sync needed.

    // ---------- Phase 3: two DRAM-free MMA + logsumexp passes ----------
    float cta_part = 0.f;
    const int bm = (w & 1) * 32, bn = (w >> 1) * 64;
#pragma unroll
    for (int t = 0; t < 2; t++) {
        float d[2][8][4];
#pragma unroll
        for (int mf = 0; mf < 2; mf++)
#pragma unroll
            for (int nf = 0; nf < 8; nf++)
#pragma unroll
                for (int q = 0; q < 4; q++) d[mf][nf][q] = 0.f;

        const uint32_t aB = sb + OFF_A + (t * 64 + bm + (lane & 15)) * ROWB
                          + ((lane >> 4) << 4);
        const uint32_t bB = sb + OFF_B + (bn + (lane & 15)) * ROWB
                          + ((lane >> 4) << 4);
#pragma unroll
        for (int ks = 0; ks < 8; ks++) {
            const uint32_t off = ks * 32;
            uint32_t a[2][4], bb[4][4];
            LDSM4(a[0], aB + off);
            LDSM4(a[1], aB + 16 * ROWB + off);
#pragma unroll
            for (int q = 0; q < 4; q++) LDSM4(bb[q], bB + q * 16 * ROWB + off);
#pragma unroll
            for (int mf = 0; mf < 2; mf++)
#pragma unroll
                for (int nf = 0; nf < 8; nf++)
                    mma_bf16(d[mf][nf], a[mf], bb[nf >> 1][nf & 1],
                             bb[nf >> 1][(nf & 1) + 2]);
        }

        // Epilogue: per-row max/sumexp over this warp's 64 columns.
        const int g = lane >> 2, t4 = lane & 3;
        float2 cbl[8];
#pragma unroll
        for (int nf = 0; nf < 8; nf++)
            cbl[nf] = *(const float2*)&cbs[bn + nf * 8 + t4 * 2];
#pragma unroll
        for (int mf = 0; mf < 2; mf++)
#pragma unroll
            for (int h = 0; h < 2; h++) {
                int row = bm + mf * 16 + h * 8 + g;
                float vv[16], mx = -1e30f;
#pragma unroll
                for (int nf = 0; nf < 8; nf++) {
                    vv[nf * 2]     = d[mf][nf][h * 2]     + cbl[nf].x;
                    vv[nf * 2 + 1] = d[mf][nf][h * 2 + 1] + cbl[nf].y;
                    mx = fmaxf(mx, fmaxf(vv[nf * 2], vv[nf * 2 + 1]));
                }
                mx = fmaxf(mx, __shfl_xor_sync(0xffffffffu, mx, 1));
                mx = fmaxf(mx, __shfl_xor_sync(0xffffffffu, mx, 2));
                float s = 0.f;
#pragma unroll
                for (int q = 0; q < 16; q++) s += __expf(2.f * (vv[q] - mx));
                s += __shfl_xor_sync(0xffffffffu, s, 1);
                s += __shfl_xor_sync(0xffffffffu, s, 2);
                if (t4 == 0) { rm[row * 4 + (w >> 1)] = mx; rs[row * 4 + (w >> 1)] = s; }
            }
        __syncthreads();

        // Merge 4 n-group partials + target column per row; fixed-order reduce.
        if (w < 2) {
            int row = w * 32 + lane;
            float tv = tl[t * 64 + row];
            float m0 = rm[row * 4],     m1 = rm[row * 4 + 1];
            float m2 = rm[row * 4 + 2], m3 = rm[row * 4 + 3];
            float M = fmaxf(fmaxf(fmaxf(m0, m1), fmaxf(m2, m3)), tv);
            float S = rs[row * 4]     * __expf(2.f * (m0 - M))
                    + rs[row * 4 + 1] * __expf(2.f * (m1 - M))
                    + rs[row * 4 + 2] * __expf(2.f * (m2 - M))
                    + rs[row * 4 + 3] * __expf(2.f * (m3 - M))
                    + __expf(2.f * (tv - M));
            float res = tv - (M + 0.5f * logf(S));
#pragma unroll
            for (int o = 16; o; o >>= 1) res += __shfl_xor_sync(0xffffffffu, res, o);
            if (lane == 0) wrd[w] = res;
        }
        __syncthreads();
        if (tid == 0) cta_part += wrd[0] + wrd[1];
        // tid0's read is ordered before the next tile's wrd write by the next
        // epilogue/merge barriers in which tid0 participates.
    }

    // ---------- completion counter + deterministic final reduction ----------
    if (tid == 0) {
        g_partials[blockIdx.x] = cta_part;
        __threadfence();
        unsigned prev = atomicAdd(&g_done, 1u);
        *last = (prev == GRID - 1) ? 1 : 0;
    }
    __syncthreads();
    if (*last) {
        __threadfence();
        red[tid] = g_partials[tid];
        __syncthreads();
#pragma unroll
        for (int s = 128; s > 0; s >>= 1) {
            if (tid < s) red[tid] += red[tid + s];
            __syncthreads();
        }
        if (tid == 0) { out[0] = -red[0] / (float)N; g_done = 0u; }
    }
}

extern "C" void kernel_launch(void* const* d_in, const int* in_sizes, int n_in,
                              void* d_out, int out_size) {
    const float* weight  = (const float*)d_in[0];
    const float* bias    = (const float*)d_in[1];
    const float* hiddens = (const float*)d_in[2];
    const float* nl      = (const float*)d_in[3];
    const void*  targets = d_in[4];
    const void*  samples = d_in[5];
    (void)n_in; (void)out_size;

    const int N = in_sizes[4];          // 32768 -> 256 CTAs x 128 rows

    cudaFuncSetAttribute(k_all, cudaFuncAttributeMaxDynamicSharedMemorySize, SMEM_TOTAL);

    k_all<<<N / 128, THREADS, SMEM_TOTAL>>>(weight, bias, hiddens, nl, targets, samples,
                                            (float*)d_out, N);
}